// round 5
// baseline (speedup 1.0000x reference)
#include <cuda_runtime.h>
#include <cuda_fp16.h>

typedef unsigned int u32;

#define B_ 512

// Pre-transposed fp16 weights [n][k]
__device__ __half g_Wz[256 * 512];   // k<256: Wz1^T, k>=256: Wz2^T
__device__ __half g_Wr[256 * 512];
__device__ __half g_Wh1[256 * 256];
__device__ __half g_Wh2[256 * 256];

// ---------------------------------------------------------------------------
// Helpers
// ---------------------------------------------------------------------------
__device__ __forceinline__ u32 smem_u32(const void* p) {
    u32 a;
    asm("{ .reg .u64 t; cvta.to.shared.u64 t, %1; cvt.u32.u64 %0, t; }" : "=r"(a) : "l"(p));
    return a;
}
__device__ __forceinline__ void ldsm4(u32* r, u32 addr) {
    asm volatile("ldmatrix.sync.aligned.m8n8.x4.shared.b16 {%0,%1,%2,%3}, [%4];"
                 : "=r"(r[0]), "=r"(r[1]), "=r"(r[2]), "=r"(r[3]) : "r"(addr));
}
__device__ __forceinline__ void mma16816(float* d, const u32* a, const u32* b) {
    asm volatile(
        "mma.sync.aligned.m16n8k16.row.col.f32.f16.f16.f32 "
        "{%0,%1,%2,%3}, {%4,%5,%6,%7}, {%8,%9}, {%0,%1,%2,%3};"
        : "+f"(d[0]), "+f"(d[1]), "+f"(d[2]), "+f"(d[3])
        : "r"(a[0]), "r"(a[1]), "r"(a[2]), "r"(a[3]), "r"(b[0]), "r"(b[1]));
}
__device__ __forceinline__ float sigmoidf_fast(float x) {
    return 1.0f / (1.0f + __expf(-x));
}
__device__ __forceinline__ void split2(float x, __half& h, __half& l) {
    h = __float2half_rn(x);
    l = __float2half_rn(x - __half2float(h));
}
__device__ __forceinline__ void cp16(u32 sdst, const void* gsrc) {
    asm volatile(
        "{ .reg .u64 p; cvta.to.global.u64 p, %1; cp.async.cg.shared.global [%0], [p], 16; }"
        :: "r"(sdst), "l"(gsrc) : "memory");
}
__device__ __forceinline__ void cp_commit() {
    asm volatile("cp.async.commit_group;" ::: "memory");
}
template <int N>
__device__ __forceinline__ void cp_wait() {
    asm volatile("cp.async.wait_group %0;" :: "n"(N) : "memory");
}

// SMEM layout
#define WSTR 144        // W/B/A tile row stride bytes (64 halfs + pad)
#define CSTR 1040       // C row stride bytes (512 halfs + pad)
#define C_HI 0
#define C_LO 66560      // 64*1040
#define WB0  133120
#define WB1  169984
#define SMEM_TOTAL 206848

// Async-copy a [rows x 64] half tile (global stride gs halfs) into padded SMEM.
__device__ __forceinline__ void cp_tile(u32 sdst, const __half* g, int rows, int gs, int tid) {
    int total = rows * 8;
    for (int i = tid; i < total; i += 256) {
        int r = i >> 3, c = i & 7;
        cp16(sdst + r * WSTR + c * 16, g + (size_t)r * gs + c * 8);
    }
}

// W-stream schedule: 24 chunks — r(8), h2(4), h1(4), z(8)
__device__ __forceinline__ const __half* seq_w(int j, int& gs, int& ck) {
    if (j < 8)       { gs = 512; ck = j * 128;              return g_Wr  + j * 64; }
    else if (j < 12) { gs = 256; ck = 512 + (j - 8) * 128;  return g_Wh2 + (j - 8) * 64; }
    else if (j < 16) { gs = 256; ck = (j - 12) * 128;       return g_Wh1 + (j - 12) * 64; }
    else             { gs = 512; ck = (j - 16) * 128;       return g_Wz  + (j - 16) * 64; }
}

// ---------------------------------------------------------------------------
// Weight transpose+convert: dst[n][koff+k] = W[k][n], fp16
// ---------------------------------------------------------------------------
__global__ __launch_bounds__(256) void conv_W(const float* __restrict__ Wz1, const float* __restrict__ Wz2,
                                              const float* __restrict__ Wr1, const float* __restrict__ Wr2,
                                              const float* __restrict__ Wh1, const float* __restrict__ Wh2) {
    int job = blockIdx.z;
    const float* src; __half* dst; int koff, stride;
    switch (job) {
        case 0:  src = Wz1; dst = g_Wz;  koff = 0;   stride = 512; break;
        case 1:  src = Wz2; dst = g_Wz;  koff = 256; stride = 512; break;
        case 2:  src = Wr1; dst = g_Wr;  koff = 0;   stride = 512; break;
        case 3:  src = Wr2; dst = g_Wr;  koff = 256; stride = 512; break;
        case 4:  src = Wh1; dst = g_Wh1; koff = 0;   stride = 256; break;
        default: src = Wh2; dst = g_Wh2; koff = 0;   stride = 256; break;
    }
    __shared__ float s[32][33];
    int tx = threadIdx.x & 31, ty = threadIdx.x >> 5;
    int n0 = blockIdx.x * 32, k0 = blockIdx.y * 32;
#pragma unroll
    for (int r = 0; r < 4; r++)
        s[ty + 8 * r][tx] = src[(size_t)(k0 + ty + 8 * r) * 256 + n0 + tx];
    __syncthreads();
#pragma unroll
    for (int r = 0; r < 4; r++)
        dst[(size_t)(n0 + ty + 8 * r) * stride + koff + k0 + tx] =
            __float2half_rn(s[tx][ty + 8 * r]);
}

// ---------------------------------------------------------------------------
// MMA on one 64(M) x 256(N) x 64(K) chunk, split-A 2-term, hi/lo de-chained.
// ahi/alo: SMEM addr of this warp's A fragment base (row stride in ams).
// bb: SMEM addr of this warp's B fragment base (stride WSTR rows).
// ---------------------------------------------------------------------------
__device__ __forceinline__ void mma_chunk(float acc[2][8][4], u32 ahi, u32 alo,
                                          u32 ams, u32 bb) {
#pragma unroll
    for (int k16 = 0; k16 < 4; k16++) {
        u32 bf[4][4];
#pragma unroll
        for (int q = 0; q < 4; q++) ldsm4(bf[q], bb + q * (16 * WSTR) + k16 * 32);
        u32 ah[2][4], al[2][4];
#pragma unroll
        for (int mi = 0; mi < 2; mi++) {
            ldsm4(ah[mi], ahi + mi * ams + k16 * 32);
            ldsm4(al[mi], alo + mi * ams + k16 * 32);
        }
        // all hi first, then all lo: same-acc RAW distance = 16 MMAs
#pragma unroll
        for (int mi = 0; mi < 2; mi++)
#pragma unroll
            for (int ni = 0; ni < 8; ni++)
                mma16816(acc[mi][ni], ah[mi], &bf[ni >> 1][(ni & 1) * 2]);
#pragma unroll
        for (int mi = 0; mi < 2; mi++)
#pragma unroll
            for (int ni = 0; ni < 8; ni++)
                mma16816(acc[mi][ni], al[mi], &bf[ni >> 1][(ni & 1) * 2]);
    }
}

// ---------------------------------------------------------------------------
// Fused GRU-GNN kernel. grid (2, 512): x = row-half, y = batch. 256 threads.
// ---------------------------------------------------------------------------
__global__ __launch_bounds__(256) void fused(
    const float* __restrict__ A, const float* __restrict__ X,
    const float* __restrict__ Hd, const float* __restrict__ bz,
    const float* __restrict__ br, const float* __restrict__ bh,
    float* __restrict__ Out)
{
    extern __shared__ char sm[];
    const u32 sb = smem_u32(sm);
    const int tid = threadIdx.x, lane = tid & 31, wid = tid >> 5;
    const int wm = wid >> 2, wn = wid & 3;
    const int half = blockIdx.x, b = blockIdx.y;
    const int node0 = half * 64;

    const float* Ap = A + (size_t)b * 16384 + (size_t)node0 * 128;

    const u32 aoffW = (u32)((wm * 32 + (lane & 15)) * WSTR + (lane >> 4) * 16);
    const u32 aoffC = (u32)((wm * 32 + (lane & 15)) * CSTR + (lane >> 4) * 16);
    const u32 boff  = (u32)((wn * 64 + (lane & 7) + ((lane >> 4) << 3)) * WSTR + ((lane >> 3) & 1) * 16);

    float accA[2][8][4], accH[2][8][4];

    // ======================= Stage 1: C = A_tile @ [X|H] =====================
#pragma unroll
    for (int p = 0; p < 2; p++) {
        const float* src = (p ? Hd : X) + (size_t)b * 32768;
#pragma unroll
        for (int mi = 0; mi < 2; mi++)
#pragma unroll
            for (int ni = 0; ni < 8; ni++)
#pragma unroll
                for (int e = 0; e < 4; e++) accA[mi][ni][e] = 0.0f;

        for (int ch = 0; ch < 2; ch++) {
            __syncthreads();
            // A tile: 64 rows x 64 k fp32 -> split hi/lo fp16 SMEM (WB1 / WB1+9216)
            {
                int r = tid >> 2, cg = tid & 3;
                const float* ar = Ap + r * 128 + ch * 64 + cg * 16;
#pragma unroll
                for (int i = 0; i < 4; i++) {
                    float4 v = *(const float4*)(ar + i * 4);
                    int c = cg * 16 + i * 4;
                    __half h0, l0, h1, l1, h2, l2, h3, l3;
                    split2(v.x, h0, l0); split2(v.y, h1, l1);
                    split2(v.z, h2, l2); split2(v.w, h3, l3);
                    *(__half2*)(sm + WB1 + r * WSTR + c * 2)            = __halves2half2(h0, h1);
                    *(__half2*)(sm + WB1 + r * WSTR + c * 2 + 4)        = __halves2half2(h2, h3);
                    *(__half2*)(sm + WB1 + 9216 + r * WSTR + c * 2)     = __halves2half2(l0, l1);
                    *(__half2*)(sm + WB1 + 9216 + r * WSTR + c * 2 + 4) = __halves2half2(l2, l3);
                }
            }
            // B tile: transpose X/H [tok][feat] fp32 -> [feat][tok] fp16 (WB0)
            {
                int tp = tid & 31, fg = tid >> 5;
                const float* s0 = src + (size_t)(ch * 64 + 2 * tp) * 256 + fg * 32;
#pragma unroll
                for (int i = 0; i < 8; i++) {
                    float4 v0 = *(const float4*)(s0 + i * 4);
                    float4 v1 = *(const float4*)(s0 + 256 + i * 4);
                    int f = fg * 32 + i * 4;
                    char* d = sm + WB0 + f * WSTR + tp * 4;
                    *(__half2*)(d)            = __halves2half2(__float2half_rn(v0.x), __float2half_rn(v1.x));
                    *(__half2*)(d + WSTR)     = __halves2half2(__float2half_rn(v0.y), __float2half_rn(v1.y));
                    *(__half2*)(d + 2 * WSTR) = __halves2half2(__float2half_rn(v0.z), __float2half_rn(v1.z));
                    *(__half2*)(d + 3 * WSTR) = __halves2half2(__float2half_rn(v0.w), __float2half_rn(v1.w));
                }
            }
            __syncthreads();
            mma_chunk(accA, sb + WB1 + aoffW, sb + WB1 + 9216 + aoffW,
                      16 * WSTR, sb + WB0 + boff);
        }
        // epilogue: split acc -> C hi/lo in SMEM
#pragma unroll
        for (int mi = 0; mi < 2; mi++)
#pragma unroll
            for (int ni = 0; ni < 8; ni++)
#pragma unroll
                for (int hh = 0; hh < 2; hh++) {
                    int row = wm * 32 + mi * 16 + (lane >> 2) + hh * 8;
                    int col = p * 256 + wn * 64 + ni * 8 + (lane & 3) * 2;
                    __half h0, l0, h1, l1;
                    split2(accA[mi][ni][hh * 2],     h0, l0);
                    split2(accA[mi][ni][hh * 2 + 1], h1, l1);
                    *(__half2*)(sm + C_HI + row * CSTR + col * 2) = __halves2half2(h0, h1);
                    *(__half2*)(sm + C_LO + row * CSTR + col * 2) = __halves2half2(l0, l1);
                }
    }
    __syncthreads();   // C visible to all; W buffers free

    // ======================= Stage 2: 24-chunk W stream ======================
#pragma unroll
    for (int mi = 0; mi < 2; mi++)
#pragma unroll
        for (int ni = 0; ni < 8; ni++)
#pragma unroll
            for (int e = 0; e < 4; e++) { accA[mi][ni][e] = 0.0f; accH[mi][ni][e] = 0.0f; }

    {
        int gs, ck;
        const __half* w = seq_w(0, gs, ck);
        cp_tile(sb + WB0, w, 256, gs, tid);
        cp_commit();
    }
    for (int j = 0; j < 24; j++) {
        u32 cur = sb + ((j & 1) ? WB1 : WB0);
        if (j < 23) {
            int gs, ck;
            const __half* w = seq_w(j + 1, gs, ck);
            cp_tile(sb + (((j + 1) & 1) ? WB1 : WB0), w, 256, gs, tid);
            cp_commit();
            cp_wait<1>();
        } else {
            cp_wait<0>();
        }
        __syncthreads();
        int gsd, ck;
        seq_w(j, gsd, ck);
        u32 ahi = sb + C_HI + ck + aoffC;
        u32 alo = sb + C_LO + ck + aoffC;
        if (j < 8 || j >= 16) mma_chunk(accA, ahi, alo, 16 * CSTR, cur + boff);
        else                  mma_chunk(accH, ahi, alo, 16 * CSTR, cur + boff);
        __syncthreads();

        if (j == 7) {
            // r = sigmoid(accA + bias_r)
#pragma unroll
            for (int mi = 0; mi < 2; mi++)
#pragma unroll
                for (int ni = 0; ni < 8; ni++)
#pragma unroll
                    for (int hh = 0; hh < 2; hh++) {
                        int node = node0 + wm * 32 + mi * 16 + (lane >> 2) + hh * 8;
                        int col  = wn * 64 + ni * 8 + (lane & 3) * 2;
                        float2 bb = *(const float2*)(br + (size_t)node * 256 + col);
                        accA[mi][ni][hh * 2]     = sigmoidf_fast(accA[mi][ni][hh * 2]     + bb.x);
                        accA[mi][ni][hh * 2 + 1] = sigmoidf_fast(accA[mi][ni][hh * 2 + 1] + bb.y);
                    }
        } else if (j == 11) {
            // accH (= P2) *= r
#pragma unroll
            for (int mi = 0; mi < 2; mi++)
#pragma unroll
                for (int ni = 0; ni < 8; ni++)
#pragma unroll
                    for (int e = 0; e < 4; e++) accH[mi][ni][e] *= accA[mi][ni][e];
        } else if (j == 15) {
            // free r -> zero for z phase
#pragma unroll
            for (int mi = 0; mi < 2; mi++)
#pragma unroll
                for (int ni = 0; ni < 8; ni++)
#pragma unroll
                    for (int e = 0; e < 4; e++) accA[mi][ni][e] = 0.0f;
        }
    }

    // ======================= Final GRU epilogue =============================
#pragma unroll
    for (int mi = 0; mi < 2; mi++)
#pragma unroll
        for (int ni = 0; ni < 8; ni++)
#pragma unroll
            for (int hh = 0; hh < 2; hh++) {
                int node = node0 + wm * 32 + mi * 16 + (lane >> 2) + hh * 8;
                int col  = wn * 64 + ni * 8 + (lane & 3) * 2;
                size_t go = ((size_t)b * 128 + node) * 256 + col;
                float2 bzv = *(const float2*)(bz + (size_t)node * 256 + col);
                float2 bhv = *(const float2*)(bh + (size_t)node * 256 + col);
                float2 hv  = *(const float2*)(Hd + go);
                float z0 = sigmoidf_fast(accA[mi][ni][hh * 2]     + bzv.x);
                float z1 = sigmoidf_fast(accA[mi][ni][hh * 2 + 1] + bzv.y);
                float t0 = tanhf(accH[mi][ni][hh * 2]     + bhv.x);
                float t1 = tanhf(accH[mi][ni][hh * 2 + 1] + bhv.y);
                float2 o;
                o.x = z0 * hv.x + (1.0f - z0) * t0;
                o.y = z1 * hv.y + (1.0f - z1) * t1;
                *(float2*)(Out + go) = o;
            }
}

// ---------------------------------------------------------------------------
extern "C" void kernel_launch(void* const* d_in, const int* in_sizes, int n_in,
                              void* d_out, int out_size) {
    (void)in_sizes; (void)n_in; (void)out_size;
    const float* X      = (const float*)d_in[0];
    const float* A      = (const float*)d_in[1];
    const float* hidden = (const float*)d_in[2];
    const float* Wz1    = (const float*)d_in[3];
    const float* Wz2    = (const float*)d_in[4];
    const float* Wr1    = (const float*)d_in[5];
    const float* Wr2    = (const float*)d_in[6];
    const float* Wh1    = (const float*)d_in[7];
    const float* Wh2    = (const float*)d_in[8];
    const float* bz     = (const float*)d_in[9];
    const float* br     = (const float*)d_in[10];
    const float* bh     = (const float*)d_in[11];
    float* out          = (float*)d_out;

    static bool attr_done = false;
    if (!attr_done) {
        cudaFuncSetAttribute(fused, cudaFuncAttributeMaxDynamicSharedMemorySize, SMEM_TOTAL);
        attr_done = true;
    }

    conv_W<<<dim3(8, 8, 6), 256>>>(Wz1, Wz2, Wr1, Wr2, Wh1, Wh2);
    fused<<<dim3(2, 512), 256, SMEM_TOTAL>>>(A, X, hidden, bz, br, bh, out);
}

// round 6
// speedup vs baseline: 1.1393x; 1.1393x over previous
#include <cuda_runtime.h>
#include <cuda_fp16.h>

typedef unsigned int u32;

#define B_    512
#define ROWS  65536   // B_*128

// ---------------------------------------------------------------------------
// Device-global scratch (allocation-free rule)
// ---------------------------------------------------------------------------
__device__ __half g_A_hi[(size_t)B_ * 128 * 128];
__device__ __half g_A_lo[(size_t)B_ * 128 * 128];
__device__ __half g_Xt[(size_t)B_ * 256 * 128];     // [b][feat][tok]
__device__ __half g_Ht[(size_t)B_ * 256 * 128];
__device__ __half g_C_hi[(size_t)ROWS * 512];       // [row][0:256]=AX,[256:512]=AH
__device__ __half g_C_lo[(size_t)ROWS * 512];
__device__ float  g_Z[(size_t)ROWS * 256];
__device__ float  g_R[(size_t)ROWS * 256];
__device__ __half g_Wz[256 * 512];                  // [n][k] k<256: Wz1^T, k>=256: Wz2^T
__device__ __half g_Wr[256 * 512];
__device__ __half g_Wh1[256 * 256];
__device__ __half g_Wh2[256 * 256];

// ---------------------------------------------------------------------------
// Helpers
// ---------------------------------------------------------------------------
__device__ __forceinline__ u32 smem_u32(const void* p) {
    u32 a;
    asm("{ .reg .u64 t; cvta.to.shared.u64 t, %1; cvt.u32.u64 %0, t; }" : "=r"(a) : "l"(p));
    return a;
}
__device__ __forceinline__ void ldsm4(u32* r, u32 addr) {
    asm volatile("ldmatrix.sync.aligned.m8n8.x4.shared.b16 {%0,%1,%2,%3}, [%4];"
                 : "=r"(r[0]), "=r"(r[1]), "=r"(r[2]), "=r"(r[3]) : "r"(addr));
}
__device__ __forceinline__ void mma16816(float* d, const u32* a, const u32* b) {
    asm volatile(
        "mma.sync.aligned.m16n8k16.row.col.f32.f16.f16.f32 "
        "{%0,%1,%2,%3}, {%4,%5,%6,%7}, {%8,%9}, {%0,%1,%2,%3};"
        : "+f"(d[0]), "+f"(d[1]), "+f"(d[2]), "+f"(d[3])
        : "r"(a[0]), "r"(a[1]), "r"(a[2]), "r"(a[3]), "r"(b[0]), "r"(b[1]));
}
__device__ __forceinline__ float sigmoidf_fast(float x) {
    return 1.0f / (1.0f + __expf(-x));
}
__device__ __forceinline__ void split2(float x, __half& h, __half& l) {
    h = __float2half_rn(x);
    l = __float2half_rn(x - __half2float(h));
}
__device__ __forceinline__ void cp16(u32 sdst, const void* gsrc) {
    asm volatile(
        "{ .reg .u64 p; cvta.to.global.u64 p, %1; cp.async.cg.shared.global [%0], [p], 16; }"
        :: "r"(sdst), "l"(gsrc) : "memory");
}
__device__ __forceinline__ void cp_commit() {
    asm volatile("cp.async.commit_group;" ::: "memory");
}
template <int N>
__device__ __forceinline__ void cp_wait() {
    asm volatile("cp.async.wait_group %0;" :: "n"(N) : "memory");
}

// SMEM tile: rows x 64 halfs, padded to 72 halfs (144 B) per row
#define STRB 144
#define OFF_AHI 0
#define OFF_ALO 18432
#define OFF_B   36864
#define BUF_SZ  55296
#define SMEM_TOTAL 110592         // double buffered

__device__ __forceinline__ void cp_tile(u32 sdst, const __half* g, int rows, int gs, int tid) {
    int total = rows * 8;
    for (int i = tid; i < total; i += 256) {
        int r = i >> 3, c = i & 7;
        cp16(sdst + r * STRB + c * 16, g + (size_t)r * gs + c * 8);
    }
}

// ---------------------------------------------------------------------------
// Conversion kernels
// ---------------------------------------------------------------------------
__global__ __launch_bounds__(256) void conv_A(const float* __restrict__ A) {
    size_t i = ((size_t)blockIdx.x * 256 + threadIdx.x) * 4;
    float4 v = *(const float4*)(A + i);
    __half h0, h1, h2, h3, l0, l1, l2, l3;
    split2(v.x, h0, l0); split2(v.y, h1, l1); split2(v.z, h2, l2); split2(v.w, h3, l3);
    __half2 hv0 = __halves2half2(h0, h1), hv1 = __halves2half2(h2, h3);
    __half2 lv0 = __halves2half2(l0, l1), lv1 = __halves2half2(l2, l3);
    *(uint2*)(g_A_hi + i) = make_uint2(*(u32*)&hv0, *(u32*)&hv1);
    *(uint2*)(g_A_lo + i) = make_uint2(*(u32*)&lv0, *(u32*)&lv1);
}

__global__ __launch_bounds__(256) void conv_XH(const float* __restrict__ X,
                                               const float* __restrict__ Hd) {
    int z = blockIdx.z;
    int b = z & (B_ - 1);
    const float* src = (z < B_) ? X : Hd;
    __half* dst = (z < B_) ? g_Xt : g_Ht;
    __shared__ float s[32][33];
    int tx = threadIdx.x & 31, ty = threadIdx.x >> 5;
    int f0 = blockIdx.x * 32, t0 = blockIdx.y * 32;
    const float* sp = src + (size_t)b * 128 * 256;
#pragma unroll
    for (int r = 0; r < 4; r++)
        s[ty + 8 * r][tx] = sp[(size_t)(t0 + ty + 8 * r) * 256 + f0 + tx];
    __syncthreads();
    size_t dbase = (size_t)b * 256 * 128;
#pragma unroll
    for (int r = 0; r < 4; r++)
        dst[dbase + (size_t)(f0 + ty + 8 * r) * 128 + t0 + tx] =
            __float2half_rn(s[tx][ty + 8 * r]);
}

__global__ __launch_bounds__(256) void conv_W(const float* __restrict__ Wz1, const float* __restrict__ Wz2,
                                              const float* __restrict__ Wr1, const float* __restrict__ Wr2,
                                              const float* __restrict__ Wh1, const float* __restrict__ Wh2) {
    int job = blockIdx.z;
    const float* src; __half* dst; int koff, stride;
    switch (job) {
        case 0:  src = Wz1; dst = g_Wz;  koff = 0;   stride = 512; break;
        case 1:  src = Wz2; dst = g_Wz;  koff = 256; stride = 512; break;
        case 2:  src = Wr1; dst = g_Wr;  koff = 0;   stride = 512; break;
        case 3:  src = Wr2; dst = g_Wr;  koff = 256; stride = 512; break;
        case 4:  src = Wh1; dst = g_Wh1; koff = 0;   stride = 256; break;
        default: src = Wh2; dst = g_Wh2; koff = 0;   stride = 256; break;
    }
    __shared__ float s[32][33];
    int tx = threadIdx.x & 31, ty = threadIdx.x >> 5;
    int n0 = blockIdx.x * 32, k0 = blockIdx.y * 32;
#pragma unroll
    for (int r = 0; r < 4; r++)
        s[ty + 8 * r][tx] = src[(size_t)(k0 + ty + 8 * r) * 256 + n0 + tx];
    __syncthreads();
#pragma unroll
    for (int r = 0; r < 4; r++)
        dst[(size_t)(n0 + ty + 8 * r) * stride + koff + k0 + tx] =
            __float2half_rn(s[tx][ty + 8 * r]);
}

// ---------------------------------------------------------------------------
// MMA on one buffered chunk: 128(M) x 128(N) x 64(K), split-A 2-term,
// de-chained: all 16 hi MMAs then all 16 lo MMAs (same-acc RAW distance 16).
// ---------------------------------------------------------------------------
__device__ __forceinline__ void mma_chunk_128x128(float acc[4][4][4], u32 sbuf,
                                                  u32 aoff, u32 boff) {
#pragma unroll
    for (int k16 = 0; k16 < 4; k16++) {
        u32 bf[2][4];
        ldsm4(bf[0], sbuf + OFF_B + boff + k16 * 32);
        ldsm4(bf[1], sbuf + OFF_B + boff + 16 * STRB + k16 * 32);
        u32 ah[4][4], al[4][4];
#pragma unroll
        for (int mi = 0; mi < 4; mi++) {
            ldsm4(ah[mi], sbuf + OFF_AHI + aoff + mi * 16 * STRB + k16 * 32);
            ldsm4(al[mi], sbuf + OFF_ALO + aoff + mi * 16 * STRB + k16 * 32);
        }
#pragma unroll
        for (int mi = 0; mi < 4; mi++)
#pragma unroll
            for (int ni = 0; ni < 4; ni++)
                mma16816(acc[mi][ni], ah[mi], &bf[ni >> 1][(ni & 1) * 2]);
#pragma unroll
        for (int mi = 0; mi < 4; mi++)
#pragma unroll
            for (int ni = 0; ni < 4; ni++)
                mma16816(acc[mi][ni], al[mi], &bf[ni >> 1][(ni & 1) * 2]);
    }
}

// ---------------------------------------------------------------------------
// k1: D[128 tok, 128 feat] = A_b @ (X|H)_b slice, -> C hi/lo fp16
// ---------------------------------------------------------------------------
__global__ __launch_bounds__(256, 2) void k1() {
    extern __shared__ char sm[];
    const int tid = threadIdx.x, lane = tid & 31, wid = tid >> 5;
    const int wm = wid >> 2, wn = wid & 3;
    const int hsel = blockIdx.x >> 1, nb = blockIdx.x & 1, b = blockIdx.y;

    const __half* Ah = g_A_hi + (size_t)b * 16384;
    const __half* Al = g_A_lo + (size_t)b * 16384;
    const __half* Bp = (hsel ? g_Ht : g_Xt) + (size_t)b * 32768 + (size_t)nb * 128 * 128;

    u32 sb = smem_u32(sm);
    u32 aoff = (u32)((wm * 64 + (lane & 15)) * STRB + (lane >> 4) * 16);
    u32 boff = (u32)((wn * 32 + (lane & 7) + ((lane >> 4) << 3)) * STRB + ((lane >> 3) & 1) * 16);

    float acc[4][4][4];
#pragma unroll
    for (int a = 0; a < 4; a++)
#pragma unroll
        for (int c = 0; c < 4; c++)
#pragma unroll
            for (int d = 0; d < 4; d++) acc[a][c][d] = 0.0f;

    cp_tile(sb + OFF_AHI, Ah, 128, 128, tid);
    cp_tile(sb + OFF_ALO, Al, 128, 128, tid);
    cp_tile(sb + OFF_B,   Bp, 128, 128, tid);
    cp_commit();
    cp_tile(sb + BUF_SZ + OFF_AHI, Ah + 64, 128, 128, tid);
    cp_tile(sb + BUF_SZ + OFF_ALO, Al + 64, 128, 128, tid);
    cp_tile(sb + BUF_SZ + OFF_B,   Bp + 64, 128, 128, tid);
    cp_commit();

    cp_wait<1>();
    __syncthreads();
    mma_chunk_128x128(acc, sb, aoff, boff);
    cp_wait<0>();
    __syncthreads();
    mma_chunk_128x128(acc, sb + BUF_SZ, aoff, boff);

    const size_t rowbase = (size_t)b * 128;
    const int colb = hsel * 256 + nb * 128 + wn * 32;
#pragma unroll
    for (int mi = 0; mi < 4; mi++) {
#pragma unroll
        for (int ni = 0; ni < 4; ni++) {
            int r0 = wm * 64 + mi * 16 + (lane >> 2);
            int c  = colb + ni * 8 + (lane & 3) * 2;
#pragma unroll
            for (int half_ = 0; half_ < 2; half_++) {
                size_t row = rowbase + r0 + half_ * 8;
                float x0 = acc[mi][ni][half_ * 2], x1 = acc[mi][ni][half_ * 2 + 1];
                __half h0, l0, h1, l1;
                split2(x0, h0, l0); split2(x1, h1, l1);
                *(__half2*)(g_C_hi + row * 512 + c) = __halves2half2(h0, h1);
                *(__half2*)(g_C_lo + row * 512 + c) = __halves2half2(l0, l1);
            }
        }
    }
}

// ---------------------------------------------------------------------------
// k2: Z/R = sigmoid(C @ W^T + bias), K=512, double-buffered pipeline.
// ---------------------------------------------------------------------------
__global__ __launch_bounds__(256, 2) void k2(const float* __restrict__ bias_z,
                                             const float* __restrict__ bias_r) {
    extern __shared__ char sm[];
    const int tid = threadIdx.x, lane = tid & 31, wid = tid >> 5;
    const int wm = wid >> 2, wn = wid & 3;
    const int gate = blockIdx.x >> 1, nb = blockIdx.x & 1, rt = blockIdx.y;

    const __half* Ah = g_C_hi + (size_t)rt * 128 * 512;
    const __half* Al = g_C_lo + (size_t)rt * 128 * 512;
    const __half* Bp = (gate ? g_Wr : g_Wz) + (size_t)nb * 128 * 512;

    u32 sb = smem_u32(sm);
    u32 aoff = (u32)((wm * 64 + (lane & 15)) * STRB + (lane >> 4) * 16);
    u32 boff = (u32)((wn * 32 + (lane & 7) + ((lane >> 4) << 3)) * STRB + ((lane >> 3) & 1) * 16);

    float acc[4][4][4];
#pragma unroll
    for (int a = 0; a < 4; a++)
#pragma unroll
        for (int c = 0; c < 4; c++)
#pragma unroll
            for (int d = 0; d < 4; d++) acc[a][c][d] = 0.0f;

    cp_tile(sb + OFF_AHI, Ah, 128, 512, tid);
    cp_tile(sb + OFF_ALO, Al, 128, 512, tid);
    cp_tile(sb + OFF_B,   Bp, 128, 512, tid);
    cp_commit();

    for (int ch = 0; ch < 8; ch++) {
        u32 cur = sb + (ch & 1) * BUF_SZ;
        if (ch < 7) {
            u32 nxt = sb + ((ch + 1) & 1) * BUF_SZ;
            cp_tile(nxt + OFF_AHI, Ah + (ch + 1) * 64, 128, 512, tid);
            cp_tile(nxt + OFF_ALO, Al + (ch + 1) * 64, 128, 512, tid);
            cp_tile(nxt + OFF_B,   Bp + (ch + 1) * 64, 128, 512, tid);
            cp_commit();
            cp_wait<1>();
        } else {
            cp_wait<0>();
        }
        __syncthreads();
        mma_chunk_128x128(acc, cur, aoff, boff);
        __syncthreads();
    }

    float* out = gate ? g_R : g_Z;
    const float* bias = gate ? bias_r : bias_z;
#pragma unroll
    for (int mi = 0; mi < 4; mi++) {
#pragma unroll
        for (int ni = 0; ni < 4; ni++) {
            int lr0 = wm * 64 + mi * 16 + (lane >> 2);
            int c   = nb * 128 + wn * 32 + ni * 8 + (lane & 3) * 2;
#pragma unroll
            for (int half_ = 0; half_ < 2; half_++) {
                int lr = lr0 + half_ * 8;
                float2 bb = *(const float2*)(bias + (size_t)lr * 256 + c);
                float2 o;
                o.x = sigmoidf_fast(acc[mi][ni][half_ * 2]     + bb.x);
                o.y = sigmoidf_fast(acc[mi][ni][half_ * 2 + 1] + bb.y);
                *(float2*)(out + ((size_t)rt * 128 + lr) * 256 + c) = o;
            }
        }
    }
}

// ---------------------------------------------------------------------------
// k3: P1 = AX@Wh1, P2 = AH@Wh2 (K=256 each), fused GRU epilogue, pipelined.
// ---------------------------------------------------------------------------
__global__ __launch_bounds__(256, 2) void k3(const float* __restrict__ bias_h,
                                             const float* __restrict__ hidden,
                                             float* __restrict__ Out) {
    extern __shared__ char sm[];
    const int tid = threadIdx.x, lane = tid & 31, wid = tid >> 5;
    const int wm = wid >> 2, wn = wid & 3;
    const int cb = blockIdx.x, rt = blockIdx.y;

    const __half* Ah = g_C_hi + (size_t)rt * 128 * 512;
    const __half* Al = g_C_lo + (size_t)rt * 128 * 512;

    u32 sb = smem_u32(sm);
    u32 aoff = (u32)((wm * 64 + (lane & 15)) * STRB + (lane >> 4) * 16);
    u32 boff = (u32)((wn * 16 + (lane & 7) + ((lane >> 4) << 3)) * STRB + ((lane >> 3) & 1) * 16);

    float acc[2][4][2][4];
#pragma unroll
    for (int p = 0; p < 2; p++)
#pragma unroll
        for (int a = 0; a < 4; a++)
#pragma unroll
            for (int c = 0; c < 2; c++)
#pragma unroll
                for (int d = 0; d < 4; d++) acc[p][a][c][d] = 0.0f;

    {
        const __half* B0 = g_Wh1 + (size_t)cb * 64 * 256;
        cp_tile(sb + OFF_AHI, Ah, 128, 512, tid);
        cp_tile(sb + OFF_ALO, Al, 128, 512, tid);
        cp_tile(sb + OFF_B,   B0, 64, 256, tid);
        cp_commit();
    }
    for (int j = 0; j < 8; j++) {
        u32 cur = sb + (j & 1) * BUF_SZ;
        if (j < 7) {
            int jn = j + 1;
            int Pn = jn >> 2, chn = jn & 3;
            const __half* Bn = (Pn ? g_Wh2 : g_Wh1) + (size_t)cb * 64 * 256;
            u32 nxt = sb + (jn & 1) * BUF_SZ;
            cp_tile(nxt + OFF_AHI, Ah + Pn * 256 + chn * 64, 128, 512, tid);
            cp_tile(nxt + OFF_ALO, Al + Pn * 256 + chn * 64, 128, 512, tid);
            cp_tile(nxt + OFF_B,   Bn + chn * 64, 64, 256, tid);
            cp_commit();
            cp_wait<1>();
        } else {
            cp_wait<0>();
        }
        __syncthreads();
        int P = j >> 2;
#pragma unroll
        for (int k16 = 0; k16 < 4; k16++) {
            u32 bf[4];
            ldsm4(bf, cur + OFF_B + boff + k16 * 32);
            u32 ah[4][4], al[4][4];
#pragma unroll
            for (int mi = 0; mi < 4; mi++) {
                ldsm4(ah[mi], cur + OFF_AHI + aoff + mi * 16 * STRB + k16 * 32);
                ldsm4(al[mi], cur + OFF_ALO + aoff + mi * 16 * STRB + k16 * 32);
            }
#pragma unroll
            for (int mi = 0; mi < 4; mi++)
#pragma unroll
                for (int ni = 0; ni < 2; ni++)
                    mma16816(acc[P][mi][ni], ah[mi], &bf[ni * 2]);
#pragma unroll
            for (int mi = 0; mi < 4; mi++)
#pragma unroll
                for (int ni = 0; ni < 2; ni++)
                    mma16816(acc[P][mi][ni], al[mi], &bf[ni * 2]);
        }
        __syncthreads();
    }

#pragma unroll
    for (int mi = 0; mi < 4; mi++) {
#pragma unroll
        for (int ni = 0; ni < 2; ni++) {
            int lr0 = wm * 64 + mi * 16 + (lane >> 2);
            int c   = cb * 64 + wn * 16 + ni * 8 + (lane & 3) * 2;
#pragma unroll
            for (int half_ = 0; half_ < 2; half_++) {
                int lr = lr0 + half_ * 8;
                size_t off = ((size_t)rt * 128 + lr) * 256 + c;
                float2 zv = *(const float2*)(g_Z + off);
                float2 rv = *(const float2*)(g_R + off);
                float2 hv = *(const float2*)(hidden + off);
                float2 bv = *(const float2*)(bias_h + (size_t)lr * 256 + c);
                float p1x = acc[0][mi][ni][half_ * 2],     p2x = acc[1][mi][ni][half_ * 2];
                float p1y = acc[0][mi][ni][half_ * 2 + 1], p2y = acc[1][mi][ni][half_ * 2 + 1];
                float2 o;
                o.x = zv.x * hv.x + (1.0f - zv.x) * tanhf(p1x + rv.x * p2x + bv.x);
                o.y = zv.y * hv.y + (1.0f - zv.y) * tanhf(p1y + rv.y * p2y + bv.y);
                *(float2*)(Out + off) = o;
            }
        }
    }
}

// ---------------------------------------------------------------------------
extern "C" void kernel_launch(void* const* d_in, const int* in_sizes, int n_in,
                              void* d_out, int out_size) {
    (void)in_sizes; (void)n_in; (void)out_size;
    const float* X      = (const float*)d_in[0];
    const float* A      = (const float*)d_in[1];
    const float* hidden = (const float*)d_in[2];
    const float* Wz1    = (const float*)d_in[3];
    const float* Wz2    = (const float*)d_in[4];
    const float* Wr1    = (const float*)d_in[5];
    const float* Wr2    = (const float*)d_in[6];
    const float* Wh1    = (const float*)d_in[7];
    const float* Wh2    = (const float*)d_in[8];
    const float* bz     = (const float*)d_in[9];
    const float* br     = (const float*)d_in[10];
    const float* bh     = (const float*)d_in[11];
    float* out          = (float*)d_out;

    static bool attr_done = false;
    if (!attr_done) {
        cudaFuncSetAttribute(k1, cudaFuncAttributeMaxDynamicSharedMemorySize, SMEM_TOTAL);
        cudaFuncSetAttribute(k2, cudaFuncAttributeMaxDynamicSharedMemorySize, SMEM_TOTAL);
        cudaFuncSetAttribute(k3, cudaFuncAttributeMaxDynamicSharedMemorySize, SMEM_TOTAL);
        attr_done = true;
    }

    conv_A<<<8192, 256>>>(A);
    conv_XH<<<dim3(8, 4, 1024), 256>>>(X, hidden);
    conv_W<<<dim3(8, 8, 6), 256>>>(Wz1, Wz2, Wr1, Wr2, Wh1, Wh2);

    k1<<<dim3(4, 512), 256, SMEM_TOTAL>>>();
    k2<<<dim3(4, 512), 256, SMEM_TOTAL>>>(bz, br);
    k3<<<dim3(4, 512), 256, SMEM_TOTAL>>>(bh, hidden, out);
}

// round 7
// speedup vs baseline: 1.2208x; 1.0715x over previous
#include <cuda_runtime.h>
#include <cuda_fp16.h>

typedef unsigned int u32;

#define B_    512
#define ROWS  65536   // B_*128

// ---------------------------------------------------------------------------
// Device-global scratch (allocation-free rule)
// ---------------------------------------------------------------------------
__device__ __half g_A_hi[(size_t)B_ * 128 * 128];
__device__ __half g_A_lo[(size_t)B_ * 128 * 128];
__device__ __half g_Xt[(size_t)B_ * 256 * 128];     // [b][feat][tok]
__device__ __half g_Ht[(size_t)B_ * 256 * 128];
__device__ __half g_C_hi[(size_t)ROWS * 512];       // [row][0:256]=AX,[256:512]=AH
__device__ __half g_C_lo[(size_t)ROWS * 512];
__device__ float  g_Z[(size_t)ROWS * 256];
__device__ float  g_R[(size_t)ROWS * 256];
__device__ __half g_Wz[256 * 512];                  // [n][k] k<256: Wz1^T, k>=256: Wz2^T
__device__ __half g_Wr[256 * 512];
__device__ __half g_Wh1[256 * 256];
__device__ __half g_Wh2[256 * 256];

// ---------------------------------------------------------------------------
// Helpers
// ---------------------------------------------------------------------------
__device__ __forceinline__ u32 smem_u32(const void* p) {
    u32 a;
    asm("{ .reg .u64 t; cvta.to.shared.u64 t, %1; cvt.u32.u64 %0, t; }" : "=r"(a) : "l"(p));
    return a;
}
__device__ __forceinline__ void ldsm4(u32* r, u32 addr) {
    asm volatile("ldmatrix.sync.aligned.m8n8.x4.shared.b16 {%0,%1,%2,%3}, [%4];"
                 : "=r"(r[0]), "=r"(r[1]), "=r"(r[2]), "=r"(r[3]) : "r"(addr));
}
__device__ __forceinline__ void mma16816(float* d, const u32* a, const u32* b) {
    asm volatile(
        "mma.sync.aligned.m16n8k16.row.col.f32.f16.f16.f32 "
        "{%0,%1,%2,%3}, {%4,%5,%6,%7}, {%8,%9}, {%0,%1,%2,%3};"
        : "+f"(d[0]), "+f"(d[1]), "+f"(d[2]), "+f"(d[3])
        : "r"(a[0]), "r"(a[1]), "r"(a[2]), "r"(a[3]), "r"(b[0]), "r"(b[1]));
}
__device__ __forceinline__ float sigmoidf_fast(float x) {
    return 1.0f / (1.0f + __expf(-x));
}
__device__ __forceinline__ void split2(float x, __half& h, __half& l) {
    h = __float2half_rn(x);
    l = __float2half_rn(x - __half2float(h));
}
__device__ __forceinline__ void cp16(u32 sdst, const void* gsrc) {
    asm volatile(
        "{ .reg .u64 p; cvta.to.global.u64 p, %1; cp.async.cg.shared.global [%0], [p], 16; }"
        :: "r"(sdst), "l"(gsrc) : "memory");
}
__device__ __forceinline__ void cp_commit() {
    asm volatile("cp.async.commit_group;" ::: "memory");
}
template <int N>
__device__ __forceinline__ void cp_wait() {
    asm volatile("cp.async.wait_group %0;" :: "n"(N) : "memory");
}

// Tiles: rows x 32 halfs, padded to 80 B/row (conflict-free for ldsm & stride-20-word pattern)
#define STRB 80
#define OFF_AHI 0
#define OFF_ALO 10240     // 128*80
#define OFF_B   20480
#define BUF_SZ  25600     // + 64*80 B-tile
#define SMEM_TOTAL 51200  // 2 stages; 3 CTAs/SM -> 153.6 KB

// Async-copy a [rows x 32] half tile (global stride gs halfs) into padded SMEM.
__device__ __forceinline__ void cp_tile(u32 sdst, const __half* g, int rows, int gs, int tid) {
    int total = rows * 4;
    for (int i = tid; i < total; i += 256) {
        int r = i >> 2, c = i & 3;
        cp16(sdst + r * STRB + c * 16, g + (size_t)r * gs + c * 8);
    }
}

// ---------------------------------------------------------------------------
// Conversion kernels
// ---------------------------------------------------------------------------
__global__ __launch_bounds__(256) void conv_A(const float* __restrict__ A) {
    size_t i = ((size_t)blockIdx.x * 256 + threadIdx.x) * 4;
    float4 v = *(const float4*)(A + i);
    __half h0, h1, h2, h3, l0, l1, l2, l3;
    split2(v.x, h0, l0); split2(v.y, h1, l1); split2(v.z, h2, l2); split2(v.w, h3, l3);
    __half2 hv0 = __halves2half2(h0, h1), hv1 = __halves2half2(h2, h3);
    __half2 lv0 = __halves2half2(l0, l1), lv1 = __halves2half2(l2, l3);
    *(uint2*)(g_A_hi + i) = make_uint2(*(u32*)&hv0, *(u32*)&hv1);
    *(uint2*)(g_A_lo + i) = make_uint2(*(u32*)&lv0, *(u32*)&lv1);
}

__global__ __launch_bounds__(256) void conv_XH(const float* __restrict__ X,
                                               const float* __restrict__ Hd) {
    int z = blockIdx.z;
    int b = z & (B_ - 1);
    const float* src = (z < B_) ? X : Hd;
    __half* dst = (z < B_) ? g_Xt : g_Ht;
    __shared__ float s[32][33];
    int tx = threadIdx.x & 31, ty = threadIdx.x >> 5;
    int f0 = blockIdx.x * 32, t0 = blockIdx.y * 32;
    const float* sp = src + (size_t)b * 128 * 256;
#pragma unroll
    for (int r = 0; r < 4; r++)
        s[ty + 8 * r][tx] = sp[(size_t)(t0 + ty + 8 * r) * 256 + f0 + tx];
    __syncthreads();
    size_t dbase = (size_t)b * 256 * 128;
#pragma unroll
    for (int r = 0; r < 4; r++)
        dst[dbase + (size_t)(f0 + ty + 8 * r) * 128 + t0 + tx] =
            __float2half_rn(s[tx][ty + 8 * r]);
}

__global__ __launch_bounds__(256) void conv_W(const float* __restrict__ Wz1, const float* __restrict__ Wz2,
                                              const float* __restrict__ Wr1, const float* __restrict__ Wr2,
                                              const float* __restrict__ Wh1, const float* __restrict__ Wh2) {
    int job = blockIdx.z;
    const float* src; __half* dst; int koff, stride;
    switch (job) {
        case 0:  src = Wz1; dst = g_Wz;  koff = 0;   stride = 512; break;
        case 1:  src = Wz2; dst = g_Wz;  koff = 256; stride = 512; break;
        case 2:  src = Wr1; dst = g_Wr;  koff = 0;   stride = 512; break;
        case 3:  src = Wr2; dst = g_Wr;  koff = 256; stride = 512; break;
        case 4:  src = Wh1; dst = g_Wh1; koff = 0;   stride = 256; break;
        default: src = Wh2; dst = g_Wh2; koff = 0;   stride = 256; break;
    }
    __shared__ float s[32][33];
    int tx = threadIdx.x & 31, ty = threadIdx.x >> 5;
    int n0 = blockIdx.x * 32, k0 = blockIdx.y * 32;
#pragma unroll
    for (int r = 0; r < 4; r++)
        s[ty + 8 * r][tx] = src[(size_t)(k0 + ty + 8 * r) * 256 + n0 + tx];
    __syncthreads();
#pragma unroll
    for (int r = 0; r < 4; r++)
        dst[(size_t)(n0 + ty + 8 * r) * stride + koff + k0 + tx] =
            __float2half_rn(s[tx][ty + 8 * r]);
}

// ---------------------------------------------------------------------------
// MMA on one buffered chunk: warp tile 32(M) x 32(N), K=32, split-A 2-term.
// ---------------------------------------------------------------------------
__device__ __forceinline__ void mma_chunk32(float acc[2][4][4], u32 sbuf,
                                            u32 aoff, u32 boff) {
#pragma unroll
    for (int k16 = 0; k16 < 2; k16++) {
        u32 bf[2][4];
        ldsm4(bf[0], sbuf + OFF_B + boff + k16 * 32);
        ldsm4(bf[1], sbuf + OFF_B + boff + 16 * STRB + k16 * 32);
        u32 ah[2][4], al[2][4];
#pragma unroll
        for (int mi = 0; mi < 2; mi++) {
            ldsm4(ah[mi], sbuf + OFF_AHI + aoff + mi * 16 * STRB + k16 * 32);
            ldsm4(al[mi], sbuf + OFF_ALO + aoff + mi * 16 * STRB + k16 * 32);
        }
#pragma unroll
        for (int mi = 0; mi < 2; mi++)
#pragma unroll
            for (int ni = 0; ni < 4; ni++)
                mma16816(acc[mi][ni], ah[mi], &bf[ni >> 1][(ni & 1) * 2]);
#pragma unroll
        for (int mi = 0; mi < 2; mi++)
#pragma unroll
            for (int ni = 0; ni < 4; ni++)
                mma16816(acc[mi][ni], al[mi], &bf[ni >> 1][(ni & 1) * 2]);
    }
}

// ---------------------------------------------------------------------------
// k1: C[128 tok, 64 feat] = A_b @ (X|H)_b slice -> C hi/lo fp16
// grid (8, 512): x = hsel*4 + nb, y = batch. 8 warps, 4(M)x2(N) of 32x32.
// ---------------------------------------------------------------------------
__global__ __launch_bounds__(256, 3) void k1() {
    extern __shared__ char sm[];
    const int tid = threadIdx.x, lane = tid & 31, wid = tid >> 5;
    const int wm = wid >> 1, wn = wid & 1;
    const int hsel = blockIdx.x >> 2, nb = blockIdx.x & 3, b = blockIdx.y;

    const __half* Ah = g_A_hi + (size_t)b * 16384;
    const __half* Al = g_A_lo + (size_t)b * 16384;
    const __half* Bp = (hsel ? g_Ht : g_Xt) + (size_t)b * 32768 + (size_t)nb * 64 * 128;

    const u32 sb = smem_u32(sm);
    const u32 aoff = (u32)((wm * 32 + (lane & 15)) * STRB + (lane >> 4) * 16);
    const u32 boff = (u32)((wn * 32 + (lane & 7) + ((lane >> 4) << 3)) * STRB + ((lane >> 3) & 1) * 16);

    float acc[2][4][4];
#pragma unroll
    for (int a = 0; a < 2; a++)
#pragma unroll
        for (int c = 0; c < 4; c++)
#pragma unroll
            for (int d = 0; d < 4; d++) acc[a][c][d] = 0.0f;

    cp_tile(sb + OFF_AHI, Ah, 128, 128, tid);
    cp_tile(sb + OFF_ALO, Al, 128, 128, tid);
    cp_tile(sb + OFF_B,   Bp, 64, 128, tid);
    cp_commit();

    for (int ch = 0; ch < 4; ch++) {
        u32 cur = sb + (ch & 1) * BUF_SZ;
        if (ch < 3) {
            u32 nxt = sb + ((ch + 1) & 1) * BUF_SZ;
            cp_tile(nxt + OFF_AHI, Ah + (ch + 1) * 32, 128, 128, tid);
            cp_tile(nxt + OFF_ALO, Al + (ch + 1) * 32, 128, 128, tid);
            cp_tile(nxt + OFF_B,   Bp + (ch + 1) * 32, 64, 128, tid);
            cp_commit();
            cp_wait<1>();
        } else {
            cp_wait<0>();
        }
        __syncthreads();
        mma_chunk32(acc, cur, aoff, boff);
        __syncthreads();
    }

    const size_t rowbase = (size_t)b * 128;
    const int colb = hsel * 256 + nb * 64 + wn * 32;
#pragma unroll
    for (int mi = 0; mi < 2; mi++)
#pragma unroll
        for (int ni = 0; ni < 4; ni++)
#pragma unroll
            for (int hh = 0; hh < 2; hh++) {
                size_t row = rowbase + wm * 32 + mi * 16 + (lane >> 2) + hh * 8;
                int c = colb + ni * 8 + (lane & 3) * 2;
                float x0 = acc[mi][ni][hh * 2], x1 = acc[mi][ni][hh * 2 + 1];
                __half h0, l0, h1, l1;
                split2(x0, h0, l0); split2(x1, h1, l1);
                *(__half2*)(g_C_hi + row * 512 + c) = __halves2half2(h0, h1);
                *(__half2*)(g_C_lo + row * 512 + c) = __halves2half2(l0, l1);
            }
}

// ---------------------------------------------------------------------------
// k2: Z/R = sigmoid(C @ W^T + bias), K=512 (16 chunks).
// grid (8, 512): x = gate*4 + nb, y = rowtile.
// ---------------------------------------------------------------------------
__global__ __launch_bounds__(256, 3) void k2(const float* __restrict__ bias_z,
                                             const float* __restrict__ bias_r) {
    extern __shared__ char sm[];
    const int tid = threadIdx.x, lane = tid & 31, wid = tid >> 5;
    const int wm = wid >> 1, wn = wid & 1;
    const int gate = blockIdx.x >> 2, nb = blockIdx.x & 3, rt = blockIdx.y;

    const __half* Ah = g_C_hi + (size_t)rt * 128 * 512;
    const __half* Al = g_C_lo + (size_t)rt * 128 * 512;
    const __half* Bp = (gate ? g_Wr : g_Wz) + (size_t)nb * 64 * 512;

    const u32 sb = smem_u32(sm);
    const u32 aoff = (u32)((wm * 32 + (lane & 15)) * STRB + (lane >> 4) * 16);
    const u32 boff = (u32)((wn * 32 + (lane & 7) + ((lane >> 4) << 3)) * STRB + ((lane >> 3) & 1) * 16);

    float acc[2][4][4];
#pragma unroll
    for (int a = 0; a < 2; a++)
#pragma unroll
        for (int c = 0; c < 4; c++)
#pragma unroll
            for (int d = 0; d < 4; d++) acc[a][c][d] = 0.0f;

    cp_tile(sb + OFF_AHI, Ah, 128, 512, tid);
    cp_tile(sb + OFF_ALO, Al, 128, 512, tid);
    cp_tile(sb + OFF_B,   Bp, 64, 512, tid);
    cp_commit();

    for (int ch = 0; ch < 16; ch++) {
        u32 cur = sb + (ch & 1) * BUF_SZ;
        if (ch < 15) {
            u32 nxt = sb + ((ch + 1) & 1) * BUF_SZ;
            cp_tile(nxt + OFF_AHI, Ah + (ch + 1) * 32, 128, 512, tid);
            cp_tile(nxt + OFF_ALO, Al + (ch + 1) * 32, 128, 512, tid);
            cp_tile(nxt + OFF_B,   Bp + (ch + 1) * 32, 64, 512, tid);
            cp_commit();
            cp_wait<1>();
        } else {
            cp_wait<0>();
        }
        __syncthreads();
        mma_chunk32(acc, cur, aoff, boff);
        __syncthreads();
    }

    float* out = gate ? g_R : g_Z;
    const float* bias = gate ? bias_r : bias_z;
#pragma unroll
    for (int mi = 0; mi < 2; mi++)
#pragma unroll
        for (int ni = 0; ni < 4; ni++)
#pragma unroll
            for (int hh = 0; hh < 2; hh++) {
                int lr = wm * 32 + mi * 16 + (lane >> 2) + hh * 8;
                int c  = nb * 64 + wn * 32 + ni * 8 + (lane & 3) * 2;
                float2 bb = *(const float2*)(bias + (size_t)lr * 256 + c);
                float2 o;
                o.x = sigmoidf_fast(acc[mi][ni][hh * 2]     + bb.x);
                o.y = sigmoidf_fast(acc[mi][ni][hh * 2 + 1] + bb.y);
                *(float2*)(out + ((size_t)rt * 128 + lr) * 256 + c) = o;
            }
}

// ---------------------------------------------------------------------------
// k3: acc = AH@Wh2 (8 chunks); acc *= r; acc += AX@Wh1 (8 chunks);
//     out = z*h + (1-z)*tanh(acc + bh).   grid (4, 512).
// ---------------------------------------------------------------------------
__global__ __launch_bounds__(256, 3) void k3(const float* __restrict__ bias_h,
                                             const float* __restrict__ hidden,
                                             float* __restrict__ Out) {
    extern __shared__ char sm[];
    const int tid = threadIdx.x, lane = tid & 31, wid = tid >> 5;
    const int wm = wid >> 1, wn = wid & 1;
    const int nb = blockIdx.x, rt = blockIdx.y;

    const __half* Ah = g_C_hi + (size_t)rt * 128 * 512;
    const __half* Al = g_C_lo + (size_t)rt * 128 * 512;
    const __half* W2 = g_Wh2 + (size_t)nb * 64 * 256;
    const __half* W1 = g_Wh1 + (size_t)nb * 64 * 256;

    const u32 sb = smem_u32(sm);
    const u32 aoff = (u32)((wm * 32 + (lane & 15)) * STRB + (lane >> 4) * 16);
    const u32 boff = (u32)((wn * 32 + (lane & 7) + ((lane >> 4) << 3)) * STRB + ((lane >> 3) & 1) * 16);

    float acc[2][4][4];
#pragma unroll
    for (int a = 0; a < 2; a++)
#pragma unroll
        for (int c = 0; c < 4; c++)
#pragma unroll
            for (int d = 0; d < 4; d++) acc[a][c][d] = 0.0f;

    // chunk j: j<8 -> A cols 256+j*32 with Wh2 ; j>=8 -> A cols (j-8)*32 with Wh1
    cp_tile(sb + OFF_AHI, Ah + 256, 128, 512, tid);
    cp_tile(sb + OFF_ALO, Al + 256, 128, 512, tid);
    cp_tile(sb + OFF_B,   W2, 64, 256, tid);
    cp_commit();

    for (int j = 0; j < 16; j++) {
        u32 cur = sb + (j & 1) * BUF_SZ;
        if (j < 15) {
            int jn = j + 1;
            int acol = (jn < 8) ? (256 + jn * 32) : ((jn - 8) * 32);
            const __half* Bn = ((jn < 8) ? W2 : W1) + ((jn < 8) ? jn : (jn - 8)) * 32;
            u32 nxt = sb + ((j + 1) & 1) * BUF_SZ;
            cp_tile(nxt + OFF_AHI, Ah + acol, 128, 512, tid);
            cp_tile(nxt + OFF_ALO, Al + acol, 128, 512, tid);
            cp_tile(nxt + OFF_B,   Bn, 64, 256, tid);
            cp_commit();
            cp_wait<1>();
        } else {
            cp_wait<0>();
        }
        __syncthreads();
        mma_chunk32(acc, cur, aoff, boff);
        if (j == 7) {
            // acc = r * P2
#pragma unroll
            for (int mi = 0; mi < 2; mi++)
#pragma unroll
                for (int ni = 0; ni < 4; ni++)
#pragma unroll
                    for (int hh = 0; hh < 2; hh++) {
                        int lr = wm * 32 + mi * 16 + (lane >> 2) + hh * 8;
                        int c  = nb * 64 + wn * 32 + ni * 8 + (lane & 3) * 2;
                        float2 rv = *(const float2*)(g_R + ((size_t)rt * 128 + lr) * 256 + c);
                        acc[mi][ni][hh * 2]     *= rv.x;
                        acc[mi][ni][hh * 2 + 1] *= rv.y;
                    }
        }
        __syncthreads();
    }

#pragma unroll
    for (int mi = 0; mi < 2; mi++)
#pragma unroll
        for (int ni = 0; ni < 4; ni++)
#pragma unroll
            for (int hh = 0; hh < 2; hh++) {
                int lr = wm * 32 + mi * 16 + (lane >> 2) + hh * 8;
                int c  = nb * 64 + wn * 32 + ni * 8 + (lane & 3) * 2;
                size_t off = ((size_t)rt * 128 + lr) * 256 + c;
                float2 zv = *(const float2*)(g_Z + off);
                float2 hv = *(const float2*)(hidden + off);
                float2 bv = *(const float2*)(bias_h + (size_t)lr * 256 + c);
                float t0 = tanhf(acc[mi][ni][hh * 2]     + bv.x);
                float t1 = tanhf(acc[mi][ni][hh * 2 + 1] + bv.y);
                float2 o;
                o.x = zv.x * hv.x + (1.0f - zv.x) * t0;
                o.y = zv.y * hv.y + (1.0f - zv.y) * t1;
                *(float2*)(Out + off) = o;
            }
}

// ---------------------------------------------------------------------------
extern "C" void kernel_launch(void* const* d_in, const int* in_sizes, int n_in,
                              void* d_out, int out_size) {
    (void)in_sizes; (void)n_in; (void)out_size;
    const float* X      = (const float*)d_in[0];
    const float* A      = (const float*)d_in[1];
    const float* hidden = (const float*)d_in[2];
    const float* Wz1    = (const float*)d_in[3];
    const float* Wz2    = (const float*)d_in[4];
    const float* Wr1    = (const float*)d_in[5];
    const float* Wr2    = (const float*)d_in[6];
    const float* Wh1    = (const float*)d_in[7];
    const float* Wh2    = (const float*)d_in[8];
    const float* bz     = (const float*)d_in[9];
    const float* br     = (const float*)d_in[10];
    const float* bh     = (const float*)d_in[11];
    float* out          = (float*)d_out;

    static bool attr_done = false;
    if (!attr_done) {
        cudaFuncSetAttribute(k1, cudaFuncAttributeMaxDynamicSharedMemorySize, SMEM_TOTAL);
        cudaFuncSetAttribute(k2, cudaFuncAttributeMaxDynamicSharedMemorySize, SMEM_TOTAL);
        cudaFuncSetAttribute(k3, cudaFuncAttributeMaxDynamicSharedMemorySize, SMEM_TOTAL);
        attr_done = true;
    }

    conv_A<<<8192, 256>>>(A);
    conv_XH<<<dim3(8, 4, 1024), 256>>>(X, hidden);
    conv_W<<<dim3(8, 8, 6), 256>>>(Wz1, Wz2, Wr1, Wr2, Wh1, Wh2);

    k1<<<dim3(8, 512), 256, SMEM_TOTAL>>>();
    k2<<<dim3(8, 512), 256, SMEM_TOTAL>>>(bz, br);
    k3<<<dim3(4, 512), 256, SMEM_TOTAL>>>(bh, hidden, out);
}

// round 9
// speedup vs baseline: 1.2435x; 1.0186x over previous
#include <cuda_runtime.h>
#include <cuda_fp16.h>

typedef unsigned int u32;

#define B_    512
#define ROWS  65536   // B_*128

// ---------------------------------------------------------------------------
// Device-global scratch (allocation-free rule)
// ---------------------------------------------------------------------------
__device__ __half g_A_hi[(size_t)B_ * 128 * 128];
__device__ __half g_A_lo[(size_t)B_ * 128 * 128];
__device__ __half g_Xt[(size_t)B_ * 256 * 128];     // [b][feat][tok]
__device__ __half g_Ht[(size_t)B_ * 256 * 128];
__device__ __half g_C_hi[(size_t)ROWS * 512];       // [row][0:256]=AX,[256:512]=AH
__device__ __half g_C_lo[(size_t)ROWS * 512];
__device__ float  g_Z[(size_t)ROWS * 256];
__device__ float  g_R[(size_t)ROWS * 256];
__device__ __half g_Wz[256 * 512];                  // [n][k] k<256: Wz1^T, k>=256: Wz2^T
__device__ __half g_Wr[256 * 512];
__device__ __half g_Wh1[256 * 256];
__device__ __half g_Wh2[256 * 256];

// ---------------------------------------------------------------------------
// Helpers
// ---------------------------------------------------------------------------
__device__ __forceinline__ u32 smem_u32(const void* p) {
    u32 a;
    asm("{ .reg .u64 t; cvta.to.shared.u64 t, %1; cvt.u32.u64 %0, t; }" : "=r"(a) : "l"(p));
    return a;
}
__device__ __forceinline__ void ldsm4(u32* r, u32 addr) {
    asm volatile("ldmatrix.sync.aligned.m8n8.x4.shared.b16 {%0,%1,%2,%3}, [%4];"
                 : "=r"(r[0]), "=r"(r[1]), "=r"(r[2]), "=r"(r[3]) : "r"(addr));
}
__device__ __forceinline__ void mma16816(float* d, const u32* a, const u32* b) {
    asm volatile(
        "mma.sync.aligned.m16n8k16.row.col.f32.f16.f16.f32 "
        "{%0,%1,%2,%3}, {%4,%5,%6,%7}, {%8,%9}, {%0,%1,%2,%3};"
        : "+f"(d[0]), "+f"(d[1]), "+f"(d[2]), "+f"(d[3])
        : "r"(a[0]), "r"(a[1]), "r"(a[2]), "r"(a[3]), "r"(b[0]), "r"(b[1]));
}
__device__ __forceinline__ float sigmoidf_fast(float x) {
    return 1.0f / (1.0f + __expf(-x));
}
__device__ __forceinline__ void split2(float x, __half& h, __half& l) {
    h = __float2half_rn(x);
    l = __float2half_rn(x - __half2float(h));
}
__device__ __forceinline__ void cp16(u32 sdst, const void* gsrc) {
    asm volatile(
        "{ .reg .u64 p; cvta.to.global.u64 p, %1; cp.async.cg.shared.global [%0], [p], 16; }"
        :: "r"(sdst), "l"(gsrc) : "memory");
}
__device__ __forceinline__ void cp_commit() {
    asm volatile("cp.async.commit_group;" ::: "memory");
}
template <int N>
__device__ __forceinline__ void cp_wait() {
    asm volatile("cp.async.wait_group %0;" :: "n"(N) : "memory");
}

// Tiles: rows x 32 halfs, padded to 80 B/row
#define STRB 80
#define OFF_AHI 0
#define OFF_ALO 10240     // 128*80
#define OFF_B   20480     // 128*80 B tile
#define STAGE_SZ 30720
#define NSTAGE   3
#define SMEM_TOTAL (STAGE_SZ * NSTAGE)   // 92160; 2 CTA/SM -> 184KB

// Async-copy a [rows x 32] half tile (global stride gs halfs) into padded SMEM.
__device__ __forceinline__ void cp_tile(u32 sdst, const __half* g, int rows, int gs, int tid) {
    int total = rows * 4;
    for (int i = tid; i < total; i += 256) {
        int r = i >> 2, c = i & 3;
        cp16(sdst + r * STRB + c * 16, g + (size_t)r * gs + c * 8);
    }
}
// 128-thread variant (used when splitting work across thread halves)
__device__ __forceinline__ void cp_tile128(u32 sdst, const __half* g, int rows, int gs, int t) {
    int total = rows * 4;
    for (int i = t; i < total; i += 128) {
        int r = i >> 2, c = i & 3;
        cp16(sdst + r * STRB + c * 16, g + (size_t)r * gs + c * 8);
    }
}

// ---------------------------------------------------------------------------
// Conversion kernels
// ---------------------------------------------------------------------------
__global__ __launch_bounds__(256) void conv_A(const float* __restrict__ A) {
    size_t i = ((size_t)blockIdx.x * 256 + threadIdx.x) * 4;
    float4 v = *(const float4*)(A + i);
    __half h0, h1, h2, h3, l0, l1, l2, l3;
    split2(v.x, h0, l0); split2(v.y, h1, l1); split2(v.z, h2, l2); split2(v.w, h3, l3);
    __half2 hv0 = __halves2half2(h0, h1), hv1 = __halves2half2(h2, h3);
    __half2 lv0 = __halves2half2(l0, l1), lv1 = __halves2half2(l2, l3);
    *(uint2*)(g_A_hi + i) = make_uint2(*(u32*)&hv0, *(u32*)&hv1);
    *(uint2*)(g_A_lo + i) = make_uint2(*(u32*)&lv0, *(u32*)&lv1);
}

__global__ __launch_bounds__(256) void conv_XH(const float* __restrict__ X,
                                               const float* __restrict__ Hd) {
    int z = blockIdx.z;
    int b = z & (B_ - 1);
    const float* src = (z < B_) ? X : Hd;
    __half* dst = (z < B_) ? g_Xt : g_Ht;
    __shared__ float s[32][33];
    int tx = threadIdx.x & 31, ty = threadIdx.x >> 5;
    int f0 = blockIdx.x * 32, t0 = blockIdx.y * 32;
    const float* sp = src + (size_t)b * 128 * 256;
#pragma unroll
    for (int r = 0; r < 4; r++)
        s[ty + 8 * r][tx] = sp[(size_t)(t0 + ty + 8 * r) * 256 + f0 + tx];
    __syncthreads();
    size_t dbase = (size_t)b * 256 * 128;
#pragma unroll
    for (int r = 0; r < 4; r++)
        dst[dbase + (size_t)(f0 + ty + 8 * r) * 128 + t0 + tx] =
            __float2half_rn(s[tx][ty + 8 * r]);
}

__global__ __launch_bounds__(256) void conv_W(const float* __restrict__ Wz1, const float* __restrict__ Wz2,
                                              const float* __restrict__ Wr1, const float* __restrict__ Wr2,
                                              const float* __restrict__ Wh1, const float* __restrict__ Wh2) {
    int job = blockIdx.z;
    const float* src; __half* dst; int koff, stride;
    switch (job) {
        case 0:  src = Wz1; dst = g_Wz;  koff = 0;   stride = 512; break;
        case 1:  src = Wz2; dst = g_Wz;  koff = 256; stride = 512; break;
        case 2:  src = Wr1; dst = g_Wr;  koff = 0;   stride = 512; break;
        case 3:  src = Wr2; dst = g_Wr;  koff = 256; stride = 512; break;
        case 4:  src = Wh1; dst = g_Wh1; koff = 0;   stride = 256; break;
        default: src = Wh2; dst = g_Wh2; koff = 0;   stride = 256; break;
    }
    __shared__ float s[32][33];
    int tx = threadIdx.x & 31, ty = threadIdx.x >> 5;
    int n0 = blockIdx.x * 32, k0 = blockIdx.y * 32;
#pragma unroll
    for (int r = 0; r < 4; r++)
        s[ty + 8 * r][tx] = src[(size_t)(k0 + ty + 8 * r) * 256 + n0 + tx];
    __syncthreads();
#pragma unroll
    for (int r = 0; r < 4; r++)
        dst[(size_t)(n0 + ty + 8 * r) * stride + koff + k0 + tx] =
            __float2half_rn(s[tx][ty + 8 * r]);
}

// ---------------------------------------------------------------------------
// MMA on one stage: warp tile 32(M) x 64(N), K=32, split-A 2-term.
// ---------------------------------------------------------------------------
__device__ __forceinline__ void mma_chunk64(float acc[2][8][4], u32 sbuf,
                                            u32 aoff, u32 boff) {
#pragma unroll
    for (int k16 = 0; k16 < 2; k16++) {
        u32 bf[4][4];
#pragma unroll
        for (int q = 0; q < 4; q++)
            ldsm4(bf[q], sbuf + OFF_B + boff + q * (16 * STRB) + k16 * 32);
        u32 ah[2][4], al[2][4];
#pragma unroll
        for (int mi = 0; mi < 2; mi++) {
            ldsm4(ah[mi], sbuf + OFF_AHI + aoff + mi * 16 * STRB + k16 * 32);
            ldsm4(al[mi], sbuf + OFF_ALO + aoff + mi * 16 * STRB + k16 * 32);
        }
#pragma unroll
        for (int mi = 0; mi < 2; mi++)
#pragma unroll
            for (int ni = 0; ni < 8; ni++)
                mma16816(acc[mi][ni], ah[mi], &bf[ni >> 1][(ni & 1) * 2]);
#pragma unroll
        for (int mi = 0; mi < 2; mi++)
#pragma unroll
            for (int ni = 0; ni < 8; ni++)
                mma16816(acc[mi][ni], al[mi], &bf[ni >> 1][(ni & 1) * 2]);
    }
}

#define ZERO_ACC(acc) \
    _Pragma("unroll") for (int _a = 0; _a < 2; _a++) \
    _Pragma("unroll") for (int _c = 0; _c < 8; _c++) \
    _Pragma("unroll") for (int _d = 0; _d < 4; _d++) acc[_a][_c][_d] = 0.0f;

// ---------------------------------------------------------------------------
// k1: per (nb, b): C[128 tok, 128 cols] where cols = [X feats nb*64..+64 |
// H feats nb*64..+64]. nb in 0..3 tiles ALL 256 feats of each. grid (4, 512).
// ---------------------------------------------------------------------------
__global__ __launch_bounds__(256, 2) void k1() {
    extern __shared__ char sm[];
    const int tid = threadIdx.x, lane = tid & 31, wid = tid >> 5;
    const int wm = wid >> 1, wn = wid & 1;
    const int nb = blockIdx.x, b = blockIdx.y;

    const __half* Ah = g_A_hi + (size_t)b * 16384;
    const __half* Al = g_A_lo + (size_t)b * 16384;
    const __half* Bx = g_Xt + (size_t)b * 32768 + (size_t)nb * 64 * 128;
    const __half* Bh = g_Ht + (size_t)b * 32768 + (size_t)nb * 64 * 128;

    const u32 sb = smem_u32(sm);
    const u32 aoff = (u32)((wm * 32 + (lane & 15)) * STRB + (lane >> 4) * 16);
    const u32 boff = (u32)((wn * 64 + (lane & 7) + ((lane >> 4) << 3)) * STRB + ((lane >> 3) & 1) * 16);

    float acc[2][8][4];
    ZERO_ACC(acc);

    // load chunk ch into stage st: A hi/lo (128x32, gs 128), B = X 64 rows + H 64 rows
    auto load = [&](int ch, u32 st) {
        cp_tile(st + OFF_AHI, Ah + ch * 32, 128, 128, tid);
        cp_tile(st + OFF_ALO, Al + ch * 32, 128, 128, tid);
        if (tid < 128) cp_tile128(st + OFF_B,             Bx + ch * 32, 64, 128, tid);
        else           cp_tile128(st + OFF_B + 64 * STRB, Bh + ch * 32, 64, 128, tid - 128);
    };

    load(0, sb); cp_commit();
    load(1, sb + STAGE_SZ); cp_commit();

    for (int ch = 0; ch < 4; ch++) {
        cp_wait<1>();
        __syncthreads();
        if (ch + 2 < 4) { load(ch + 2, sb + ((ch + 2) % 3) * STAGE_SZ); cp_commit(); }
        mma_chunk64(acc, sb + (ch % 3) * STAGE_SZ, aoff, boff);
    }

    const size_t rowbase = (size_t)b * 128;
    const int colb = (wn == 0) ? (nb * 64) : (256 + nb * 64);
#pragma unroll
    for (int mi = 0; mi < 2; mi++)
#pragma unroll
        for (int ni = 0; ni < 8; ni++)
#pragma unroll
            for (int hh = 0; hh < 2; hh++) {
                size_t row = rowbase + wm * 32 + mi * 16 + (lane >> 2) + hh * 8;
                int c = colb + ni * 8 + (lane & 3) * 2;
                float x0 = acc[mi][ni][hh * 2], x1 = acc[mi][ni][hh * 2 + 1];
                __half h0, l0, h1, l1;
                split2(x0, h0, l0); split2(x1, h1, l1);
                *(__half2*)(g_C_hi + row * 512 + c) = __halves2half2(h0, h1);
                *(__half2*)(g_C_lo + row * 512 + c) = __halves2half2(l0, l1);
            }
}

// ---------------------------------------------------------------------------
// k2: Z/R = sigmoid(C @ W^T + bias), K=512 (16 chunks), N=128 per CTA.
// grid (4, 512): x = gate*2 + nb.
// ---------------------------------------------------------------------------
__global__ __launch_bounds__(256, 2) void k2(const float* __restrict__ bias_z,
                                             const float* __restrict__ bias_r) {
    extern __shared__ char sm[];
    const int tid = threadIdx.x, lane = tid & 31, wid = tid >> 5;
    const int wm = wid >> 1, wn = wid & 1;
    const int gate = blockIdx.x >> 1, nb = blockIdx.x & 1, rt = blockIdx.y;

    const __half* Ah = g_C_hi + (size_t)rt * 128 * 512;
    const __half* Al = g_C_lo + (size_t)rt * 128 * 512;
    const __half* Bp = (gate ? g_Wr : g_Wz) + (size_t)nb * 128 * 512;

    const u32 sb = smem_u32(sm);
    const u32 aoff = (u32)((wm * 32 + (lane & 15)) * STRB + (lane >> 4) * 16);
    const u32 boff = (u32)((wn * 64 + (lane & 7) + ((lane >> 4) << 3)) * STRB + ((lane >> 3) & 1) * 16);

    float acc[2][8][4];
    ZERO_ACC(acc);

    auto load = [&](int ch, u32 st) {
        cp_tile(st + OFF_AHI, Ah + ch * 32, 128, 512, tid);
        cp_tile(st + OFF_ALO, Al + ch * 32, 128, 512, tid);
        cp_tile(st + OFF_B,   Bp + ch * 32, 128, 512, tid);
    };

    load(0, sb); cp_commit();
    load(1, sb + STAGE_SZ); cp_commit();

    for (int ch = 0; ch < 16; ch++) {
        cp_wait<1>();
        __syncthreads();
        if (ch + 2 < 16) { load(ch + 2, sb + ((ch + 2) % 3) * STAGE_SZ); cp_commit(); }
        mma_chunk64(acc, sb + (ch % 3) * STAGE_SZ, aoff, boff);
    }

    float* out = gate ? g_R : g_Z;
    const float* bias = gate ? bias_r : bias_z;
#pragma unroll
    for (int mi = 0; mi < 2; mi++)
#pragma unroll
        for (int ni = 0; ni < 8; ni++)
#pragma unroll
            for (int hh = 0; hh < 2; hh++) {
                int lr = wm * 32 + mi * 16 + (lane >> 2) + hh * 8;
                int c  = nb * 128 + wn * 64 + ni * 8 + (lane & 3) * 2;
                float2 bb = *(const float2*)(bias + (size_t)lr * 256 + c);
                float2 o;
                o.x = sigmoidf_fast(acc[mi][ni][hh * 2]     + bb.x);
                o.y = sigmoidf_fast(acc[mi][ni][hh * 2 + 1] + bb.y);
                *(float2*)(out + ((size_t)rt * 128 + lr) * 256 + c) = o;
            }
}

// ---------------------------------------------------------------------------
// k3: acc = AH@Wh2 (8 chunks); acc *= r; acc += AX@Wh1 (8 chunks);
//     out = z*h + (1-z)*tanh(acc + bh).   grid (2, 512): x = nb (N=128).
// ---------------------------------------------------------------------------
__global__ __launch_bounds__(256, 2) void k3(const float* __restrict__ bias_h,
                                             const float* __restrict__ hidden,
                                             float* __restrict__ Out) {
    extern __shared__ char sm[];
    const int tid = threadIdx.x, lane = tid & 31, wid = tid >> 5;
    const int wm = wid >> 1, wn = wid & 1;
    const int nb = blockIdx.x, rt = blockIdx.y;

    const __half* Ah = g_C_hi + (size_t)rt * 128 * 512;
    const __half* Al = g_C_lo + (size_t)rt * 128 * 512;
    const __half* W2 = g_Wh2 + (size_t)nb * 128 * 256;
    const __half* W1 = g_Wh1 + (size_t)nb * 128 * 256;

    const u32 sb = smem_u32(sm);
    const u32 aoff = (u32)((wm * 32 + (lane & 15)) * STRB + (lane >> 4) * 16);
    const u32 boff = (u32)((wn * 64 + (lane & 7) + ((lane >> 4) << 3)) * STRB + ((lane >> 3) & 1) * 16);

    float acc[2][8][4];
    ZERO_ACC(acc);

    // chunk j: j<8 -> A cols 256+j*32 with Wh2 ; j>=8 -> A cols (j-8)*32 with Wh1
    auto load = [&](int j, u32 st) {
        int acol = (j < 8) ? (256 + j * 32) : ((j - 8) * 32);
        const __half* Bn = ((j < 8) ? W2 : W1) + ((j < 8) ? j : (j - 8)) * 32;
        cp_tile(st + OFF_AHI, Ah + acol, 128, 512, tid);
        cp_tile(st + OFF_ALO, Al + acol, 128, 512, tid);
        cp_tile(st + OFF_B,   Bn, 128, 256, tid);
    };

    load(0, sb); cp_commit();
    load(1, sb + STAGE_SZ); cp_commit();

    for (int j = 0; j < 16; j++) {
        cp_wait<1>();
        __syncthreads();
        if (j + 2 < 16) { load(j + 2, sb + ((j + 2) % 3) * STAGE_SZ); cp_commit(); }
        mma_chunk64(acc, sb + (j % 3) * STAGE_SZ, aoff, boff);
        if (j == 7) {
#pragma unroll
            for (int mi = 0; mi < 2; mi++)
#pragma unroll
                for (int ni = 0; ni < 8; ni++)
#pragma unroll
                    for (int hh = 0; hh < 2; hh++) {
                        int lr = wm * 32 + mi * 16 + (lane >> 2) + hh * 8;
                        int c  = nb * 128 + wn * 64 + ni * 8 + (lane & 3) * 2;
                        float2 rv = *(const float2*)(g_R + ((size_t)rt * 128 + lr) * 256 + c);
                        acc[mi][ni][hh * 2]     *= rv.x;
                        acc[mi][ni][hh * 2 + 1] *= rv.y;
                    }
        }
    }

#pragma unroll
    for (int mi = 0; mi < 2; mi++)
#pragma unroll
        for (int ni = 0; ni < 8; ni++)
#pragma unroll
            for (int hh = 0; hh < 2; hh++) {
                int lr = wm * 32 + mi * 16 + (lane >> 2) + hh * 8;
                int c  = nb * 128 + wn * 64 + ni * 8 + (lane & 3) * 2;
                size_t off = ((size_t)rt * 128 + lr) * 256 + c;
                float2 zv = *(const float2*)(g_Z + off);
                float2 hv = *(const float2*)(hidden + off);
                float2 bv = *(const float2*)(bias_h + (size_t)lr * 256 + c);
                float t0 = tanhf(acc[mi][ni][hh * 2]     + bv.x);
                float t1 = tanhf(acc[mi][ni][hh * 2 + 1] + bv.y);
                float2 o;
                o.x = zv.x * hv.x + (1.0f - zv.x) * t0;
                o.y = zv.y * hv.y + (1.0f - zv.y) * t1;
                *(float2*)(Out + off) = o;
            }
}

// ---------------------------------------------------------------------------
extern "C" void kernel_launch(void* const* d_in, const int* in_sizes, int n_in,
                              void* d_out, int out_size) {
    (void)in_sizes; (void)n_in; (void)out_size;
    const float* X      = (const float*)d_in[0];
    const float* A      = (const float*)d_in[1];
    const float* hidden = (const float*)d_in[2];
    const float* Wz1    = (const float*)d_in[3];
    const float* Wz2    = (const float*)d_in[4];
    const float* Wr1    = (const float*)d_in[5];
    const float* Wr2    = (const float*)d_in[6];
    const float* Wh1    = (const float*)d_in[7];
    const float* Wh2    = (const float*)d_in[8];
    const float* bz     = (const float*)d_in[9];
    const float* br     = (const float*)d_in[10];
    const float* bh     = (const float*)d_in[11];
    float* out          = (float*)d_out;

    static bool attr_done = false;
    if (!attr_done) {
        cudaFuncSetAttribute(k1, cudaFuncAttributeMaxDynamicSharedMemorySize, SMEM_TOTAL);
        cudaFuncSetAttribute(k2, cudaFuncAttributeMaxDynamicSharedMemorySize, SMEM_TOTAL);
        cudaFuncSetAttribute(k3, cudaFuncAttributeMaxDynamicSharedMemorySize, SMEM_TOTAL);
        attr_done = true;
    }

    conv_A<<<8192, 256>>>(A);
    conv_XH<<<dim3(8, 4, 1024), 256>>>(X, hidden);
    conv_W<<<dim3(8, 8, 6), 256>>>(Wz1, Wz2, Wr1, Wr2, Wh1, Wh2);

    k1<<<dim3(4, 512), 256, SMEM_TOTAL>>>();
    k2<<<dim3(4, 512), 256, SMEM_TOTAL>>>(bz, br);
    k3<<<dim3(2, 512), 256, SMEM_TOTAL>>>(bh, hidden, out);
}